// round 2
// baseline (speedup 1.0000x reference)
#include <cuda_runtime.h>
#include <cstdint>

// reconstruction_loss: mean(sqrt(d^2 + 1e-6)) over mosaic-gathered pixels
//   X, Y: [8, 16, 512, 512] fp32, channel c = (h%4)*4 + (w%4)
// Strategy: direct strided gather (DRAM sector traffic is irreducibly 4x useful
// bytes at 32B-sector granularity; per-warp instruction counts are negligible
// vs the memory roofline), deterministic two-kernel tree reduction (no float
// atomics -> bit-identical output on every graph replay).

#define N_ELEM (8 * 512 * 512)   // 2097152 gathered pixels
#define NBLK 1024
#define NTHR 256

__device__ float g_partial[NBLK];

__global__ void __launch_bounds__(NTHR)
msfa_loss_main(const float* __restrict__ X, const float* __restrict__ Y) {
    int t = blockIdx.x * NTHR + threadIdx.x;   // [0, 262144): one (h, w) pixel
    int h = t >> 9;                            // [0, 512)
    int w = t & 511;                           // [0, 512)
    int c = ((h & 3) << 2) | (w & 3);          // mosaic channel
    // offset within one batch: (c*512 + h)*512 + w
    size_t off = ((size_t)c << 18) + ((size_t)h << 9) + (size_t)w;

    float acc = 0.0f;
#pragma unroll
    for (int b = 0; b < 8; b++) {
        size_t o = off + ((size_t)b << 22);    // b * 16*512*512
        float x = X[o];
        float y = Y[o];
        float d = x - y;
        float s = __fmaf_rn(d, d, 1e-6f);
        acc += __fsqrt_rn(s);
    }

    // deterministic in-block reduction: warp shfl tree, then smem across warps
#pragma unroll
    for (int o = 16; o; o >>= 1)
        acc += __shfl_xor_sync(0xFFFFFFFFu, acc, o);

    __shared__ float red[NTHR / 32];
    if ((threadIdx.x & 31) == 0) red[threadIdx.x >> 5] = acc;
    __syncthreads();
    if (threadIdx.x == 0) {
        float s = 0.0f;
#pragma unroll
        for (int i = 0; i < NTHR / 32; i++) s += red[i];
        g_partial[blockIdx.x] = s;
    }
}

__global__ void __launch_bounds__(256)
msfa_loss_reduce(float* __restrict__ out) {
    int tid = threadIdx.x;
    float a = (g_partial[tid]       + g_partial[tid + 256]) +
              (g_partial[tid + 512] + g_partial[tid + 768]);
#pragma unroll
    for (int o = 16; o; o >>= 1)
        a += __shfl_xor_sync(0xFFFFFFFFu, a, o);

    __shared__ float red[8];
    if ((tid & 31) == 0) red[tid >> 5] = a;
    __syncthreads();
    if (tid == 0) {
        float s = 0.0f;
#pragma unroll
        for (int i = 0; i < 8; i++) s += red[i];
        out[0] = s * (1.0f / (float)N_ELEM);
    }
}

extern "C" void kernel_launch(void* const* d_in, const int* in_sizes, int n_in,
                              void* d_out, int out_size) {
    const float* X = (const float*)d_in[0];
    const float* Y = (const float*)d_in[1];
    msfa_loss_main<<<NBLK, NTHR>>>(X, Y);
    msfa_loss_reduce<<<1, 256>>>((float*)d_out);
}